// round 8
// baseline (speedup 1.0000x reference)
#include <cuda_runtime.h>
#include <cuda_fp16.h>

// warp3D: out[b,c,z,y,x] = trilinear gather of I at (x+fx, y+fy, z+fz)
// B=2, C=2, D=160, H=192, W=224, fp32 in/out.
//
// Pass 1: pack I -> fp16 "half4" per voxel (8 B):
//         It[b,z,y,x] = h(c0[x]), h(c1[x]), h(c0[x+1]), h(c1[x+1])
// Pass 2: each thread handles an X-PAIR of voxels (x, x+1). Their gather
//         entries sit at x0 and ~x0+1 in the same rows -> the pair's 8
//         gathers touch ~the line set of one voxel's 4. Flow/out accesses
//         become float2.

#define Wd 224
#define Hd 192
#define Dd 160
#define Bd 2
#define HWd (Hd * Wd)            // 43008
#define DHWd (Dd * HWd)          // 6881280

__device__ __forceinline__ unsigned int h2_to_u(__half2 h) {
    return *reinterpret_cast<unsigned int*>(&h);
}
__device__ __forceinline__ __half2 u_to_h2(unsigned int u) {
    return *reinterpret_cast<__half2*>(&u);
}

// 13.76M voxels * 8B = 110 MB scratch
__device__ uint2 g_It[(long)Bd * DHWd];

// Pack: 2 voxels/thread, float2 loads, one STG.128 per pair.
__global__ __launch_bounds__(224) void pack_kernel(const float* __restrict__ I)
{
    const int m = threadIdx.x;                 // 0..111  (x pair = 2m, 2m+1)
    const int y = blockIdx.x * 2 + threadIdx.y;
    const int z = blockIdx.y;
    const int b = blockIdx.z;

    const int x = 2 * m;
    const int s = z * HWd + y * Wd + x;
    const float* __restrict__ I0 = I + (long)b * 2 * DHWd;
    const float* __restrict__ I1 = I0 + DHWd;

    const float2 a = __ldg((const float2*)(I0 + s));   // c0[x], c0[x+1]
    const float2 c = __ldg((const float2*)(I1 + s));   // c1[x], c1[x+1]
    const int sn = s - x + min(x + 2, Wd - 1);          // x+2, edge-clamped
    const float n0 = __ldg(I0 + sn);
    const float n1 = __ldg(I1 + sn);

    const unsigned int lo0 = h2_to_u(__floats2half2_rn(a.x, c.x));
    const unsigned int mid = h2_to_u(__floats2half2_rn(a.y, c.y));
    const unsigned int hi1 = h2_to_u(__floats2half2_rn(n0, n1));

    uint4 v;
    v.x = lo0; v.y = mid;      // voxel x
    v.z = mid; v.w = hi1;      // voxel x+1
    *reinterpret_cast<uint4*>(g_It + (long)b * DHWd + s) = v;
}

// Gather: block (112,2) = 224 thr covering 2 y-rows; thread = x-pair.
__global__ __launch_bounds__(224) void warp3d_kernel(
    const float* __restrict__ flow,
    float* __restrict__ out)
{
    const int m = threadIdx.x;                // 0..111
    const int y = blockIdx.x * 2 + threadIdx.y;
    const int z = blockIdx.y;
    const int b = blockIdx.z;

    const int x0p = 2 * m;                    // even x of the pair
    const int s = z * HWd + y * Wd + x0p;     // float2-aligned

    const float* __restrict__ fb = flow + (long)b * 3 * DHWd;
    const uint2* __restrict__ Ic = g_It + (long)b * DHWd;
    float* __restrict__ ob = out + (long)b * 2 * DHWd;

    // flow for both voxels: 3 x LDG.64
    const float2 fx2 = __ldg((const float2*)(fb + s));
    const float2 fy2 = __ldg((const float2*)(fb + s + DHWd));
    const float2 fz2 = __ldg((const float2*)(fb + s + 2L * DHWd));

    float w00[2], w10[2], w01[2], w11[2], dzv[2], ezv[2];
    uint2 A0[2], A1[2], B0[2], B1[2];
    bool  xeq[2];

#pragma unroll
    for (int v = 0; v < 2; ++v) {
        const int x = x0p + v;
        const float xf = (v ? fx2.y : fx2.x) + (float)x;
        const float yf = (v ? fy2.y : fy2.x) + (float)y;
        const float zf = (v ? fz2.y : fz2.x) + (float)z;

        int x0 = (int)floorf(xf);
        int y0 = (int)floorf(yf);
        int z0 = (int)floorf(zf);
        // upper corner from UNclamped lower+1, then clamp (matches ref)
        const int x1 = min(max(x0 + 1, 0), Wd - 1);
        const int y1 = min(max(y0 + 1, 0), Hd - 1);
        const int z1 = min(max(z0 + 1, 0), Dd - 1);
        x0 = min(max(x0, 0), Wd - 1);
        y0 = min(max(y0, 0), Hd - 1);
        z0 = min(max(z0, 0), Dd - 1);

        const float dx = (float)x1 - xf;
        const float dy = (float)y1 - yf;
        const float dz = (float)z1 - zf;
        const float ex = 1.0f - dx;
        const float ey = 1.0f - dy;

        w00[v] = dx * dy;
        w10[v] = dx * ey;
        w01[v] = ex * dy;
        w11[v] = ex * ey;
        dzv[v] = dz;
        ezv[v] = 1.0f - dz;
        xeq[v] = (x1 == x0);

        const int r00 = z0 * HWd + y0 * Wd + x0;
        const int r10 = z0 * HWd + y1 * Wd + x0;
        const int r01 = z1 * HWd + y0 * Wd + x0;
        const int r11 = z1 * HWd + y1 * Wd + x0;

        A0[v] = __ldg(Ic + r00);
        A1[v] = __ldg(Ic + r10);
        B0[v] = __ldg(Ic + r01);
        B1[v] = __ldg(Ic + r11);
    }

    float2 o0, o1;   // (vox0, vox1) for channel 0 / channel 1
#pragma unroll
    for (int v = 0; v < 2; ++v) {
        if (xeq[v]) {   // below-range x clamp: hi pair := lo pair
            A0[v].y = A0[v].x;
            A1[v].y = A1[v].x;
            B0[v].y = B0[v].x;
            B1[v].y = B1[v].x;
        }

        const float2 a0l = __half22float2(u_to_h2(A0[v].x));
        const float2 a0h = __half22float2(u_to_h2(A0[v].y));
        const float2 a1l = __half22float2(u_to_h2(A1[v].x));
        const float2 a1h = __half22float2(u_to_h2(A1[v].y));
        const float2 b0l = __half22float2(u_to_h2(B0[v].x));
        const float2 b0h = __half22float2(u_to_h2(B0[v].y));
        const float2 b1l = __half22float2(u_to_h2(B1[v].x));
        const float2 b1h = __half22float2(u_to_h2(B1[v].y));

        const float p0c0 = w00[v]*a0l.x + w10[v]*a1l.x + w01[v]*a0h.x + w11[v]*a1h.x;
        const float p0c1 = w00[v]*a0l.y + w10[v]*a1l.y + w01[v]*a0h.y + w11[v]*a1h.y;
        const float p1c0 = w00[v]*b0l.x + w10[v]*b1l.x + w01[v]*b0h.x + w11[v]*b1h.x;
        const float p1c1 = w00[v]*b0l.y + w10[v]*b1l.y + w01[v]*b0h.y + w11[v]*b1h.y;

        const float c0 = dzv[v] * p0c0 + ezv[v] * p1c0;
        const float c1 = dzv[v] * p0c1 + ezv[v] * p1c1;
        if (v == 0) { o0.x = c0; o1.x = c1; }
        else        { o0.y = c0; o1.y = c1; }
    }

    // 2 x STG.64
    *reinterpret_cast<float2*>(ob + s)        = o0;
    *reinterpret_cast<float2*>(ob + s + DHWd) = o1;
}

extern "C" void kernel_launch(void* const* d_in, const int* in_sizes, int n_in,
                              void* d_out, int out_size)
{
    const float* I    = (const float*)d_in[0];
    const float* flow = (const float*)d_in[1];
    float* out        = (float*)d_out;

    dim3 block(112, 2, 1);                  // 224 thr
    dim3 grid(Hd / 2, Dd, Bd);              // 96 x 160 x 2

    pack_kernel<<<grid, block>>>(I);
    warp3d_kernel<<<grid, block>>>(flow, out);
}